// round 13
// baseline (speedup 1.0000x reference)
#include <cuda_runtime.h>
#include <cuda_bf16.h>
#include <cstdint>

// ==========================================================================
// LORI_FC: out = x @ blockdiag(D) + (x @ Wl^T) @ Wr^T + (b_right + bias)
//   x [8192,4096] f32. Split-bf16 hi/lo (3 passes), HMMA m16n8k16, f32 accum.
// LDG -> swizzled STS -> ldmatrix.x4 -> MMA, software-pipelined with
// double-buffered smem (2 x 48 KB). x prefetched into registers across the
// MMA block to hide DRAM latency.
//   prep: split Wl/Wr/D^T -> bf16 hi/lo, bsum = br + bias
//   k1:   t_part[s] = x[:, 512s:512s+512] @ Wl^T slice   (512 CTAs, pipelined)
//   k1b:  t = sum partials -> bf16 hi/lo
//   k2:   out[128, 64j] = xb_j @ D_j + t @ Wr_j^T + bsum (512 CTAs x 8 j's)
// ==========================================================================

#define M_ROWS 8192
#define IN_F   4096
#define OUT_F  4096
#define KSPLIT 8
#define NJ     8

__device__ __align__(16) float g_tpart[KSPLIT][M_ROWS * 64];       // 16 MB
__device__ __align__(16) __nv_bfloat16 g_thi[M_ROWS * 64];
__device__ __align__(16) __nv_bfloat16 g_tlo[M_ROWS * 64];
__device__ __align__(16) __nv_bfloat16 g_wlh[64 * IN_F];
__device__ __align__(16) __nv_bfloat16 g_wll[64 * IN_F];
__device__ __align__(16) __nv_bfloat16 g_wrh[OUT_F * 64];
__device__ __align__(16) __nv_bfloat16 g_wrl[OUT_F * 64];
__device__ __align__(16) __nv_bfloat16 g_dth[64 * 64 * 64];        // [j][n][k]
__device__ __align__(16) __nv_bfloat16 g_dtl[64 * 64 * 64];
__device__ __align__(16) float g_bsum[OUT_F];

// per-buffer layout (48 KB): Ah 16K | Al 16K | Bh 8K | Bl 8K;  2 buffers
#define SM_AH 0
#define SM_AL 16384
#define SM_BH 32768
#define SM_BL 40960
#define BUFSZ 49152
#define SMEM_BYTES (2 * BUFSZ)   // 98304

#define MMA_BF16(C, A, B0, B1)                                                \
    asm volatile(                                                             \
        "mma.sync.aligned.m16n8k16.row.col.f32.bf16.bf16.f32 "                \
        "{%0,%1,%2,%3}, {%4,%5,%6,%7}, {%8,%9}, {%0,%1,%2,%3};"               \
        : "+f"((C)[0]), "+f"((C)[1]), "+f"((C)[2]), "+f"((C)[3])              \
        : "r"((A)[0]), "r"((A)[1]), "r"((A)[2]), "r"((A)[3]), "r"(B0), "r"(B1))

#define LDSM4(R, A)                                                           \
    asm volatile("ldmatrix.sync.aligned.m8n8.x4.shared.b16 {%0,%1,%2,%3}, [%4];" \
        : "=r"((R)[0]), "=r"((R)[1]), "=r"((R)[2]), "=r"((R)[3]) : "r"(A))

__device__ __forceinline__ uint32_t smem_u32(const void* p) {
    uint32_t a;
    asm("{ .reg .u64 t; cvta.to.shared.u64 t, %1; cvt.u32.u64 %0, t; }"
        : "=r"(a) : "l"(p));
    return a;
}

__device__ __forceinline__ void split2pack(float f0, float f1,
                                           uint32_t& hi, uint32_t& lo) {
    uint32_t h;
    asm("cvt.rn.bf16x2.f32 %0, %1, %2;" : "=r"(h) : "f"(f1), "f"(f0));
    float h0 = __uint_as_float(h << 16);
    float h1 = __uint_as_float(h & 0xffff0000u);
    float r0 = f0 - h0, r1 = f1 - h1;
    asm("cvt.rn.bf16x2.f32 %0, %1, %2;" : "=r"(lo) : "f"(r1), "f"(r0));
    hi = h;
}

// ---------------- staging ----------------
// x block 128x64 f32: LDG into regs (prefetch) ...
__device__ __forceinline__ void ldg_x(float4 (&v)[8], const float* xp, int tid) {
    const int r = tid >> 1, h = tid & 1;
    const float* p = xp + (size_t)r * IN_F + h * 32;
#pragma unroll
    for (int i = 0; i < 8; i++) v[i] = ((const float4*)p)[i];
}
// ... then split + STS into A tiles of buffer `sbuf`
__device__ __forceinline__ void sts_x(uint32_t sbuf, const float4 (&v)[8], int tid) {
    const int r = tid >> 1, h = tid & 1;
    const uint32_t dbase = sbuf + SM_AH + (uint32_t)r * 128 + (uint32_t)h * 64;
    const uint32_t xv = (uint32_t)(r & 7) << 4;
#pragma unroll
    for (int i = 0; i < 8; i++) {
        uint32_t h0, l0, h1, l1;
        split2pack(v[i].x, v[i].y, h0, l0);
        split2pack(v[i].z, v[i].w, h1, l1);
        uint32_t d = (dbase + i * 8) ^ xv;
        asm volatile("st.shared.v2.b32 [%0], {%1,%2};" :: "r"(d), "r"(h0), "r"(h1));
        asm volatile("st.shared.v2.b32 [%0], {%1,%2};" :: "r"(d + 16384), "r"(l0), "r"(l1));
    }
}

// pre-split bf16 [64][64] contiguous -> B tiles of buffer
__device__ __forceinline__ void stage_B64(uint32_t sbuf, const __nv_bfloat16* hi,
                                          const __nv_bfloat16* lo, int tid) {
#pragma unroll
    for (int c = tid; c < 512; c += 256) {
        uint4 v = ((const uint4*)hi)[c];
        uint4 w = ((const uint4*)lo)[c];
        uint32_t d = (sbuf + SM_BH + (uint32_t)c * 16) ^ ((((uint32_t)c >> 3) & 7) << 4);
        asm volatile("st.shared.v4.b32 [%0], {%1,%2,%3,%4};"
                     :: "r"(d), "r"(v.x), "r"(v.y), "r"(v.z), "r"(v.w));
        asm volatile("st.shared.v4.b32 [%0], {%1,%2,%3,%4};"
                     :: "r"(d + 8192), "r"(w.x), "r"(w.y), "r"(w.z), "r"(w.w));
    }
}

// Wl chunk (row stride IN_F), cols [kbase, kbase+64) -> B tiles
__device__ __forceinline__ void stage_Bwl(uint32_t sbuf, int kbase, int tid) {
#pragma unroll
    for (int c = tid; c < 512; c += 256) {
        int n = c >> 3, kp = c & 7;
        uint4 v = *(const uint4*)(g_wlh + (size_t)n * IN_F + kbase + kp * 8);
        uint4 w = *(const uint4*)(g_wll + (size_t)n * IN_F + kbase + kp * 8);
        uint32_t d = (sbuf + SM_BH + (uint32_t)c * 16) ^ (((uint32_t)n & 7) << 4);
        asm volatile("st.shared.v4.b32 [%0], {%1,%2,%3,%4};"
                     :: "r"(d), "r"(v.x), "r"(v.y), "r"(v.z), "r"(v.w));
        asm volatile("st.shared.v4.b32 [%0], {%1,%2,%3,%4};"
                     :: "r"(d + 8192), "r"(w.x), "r"(w.y), "r"(w.z), "r"(w.w));
    }
}

// pre-split t hi/lo 128x64 contiguous -> A tiles
__device__ __forceinline__ void stage_At(uint32_t sbuf, const __nv_bfloat16* hi,
                                         const __nv_bfloat16* lo, int tid) {
#pragma unroll
    for (int c = tid; c < 1024; c += 256) {
        uint4 v = ((const uint4*)hi)[c];
        uint4 w = ((const uint4*)lo)[c];
        uint32_t d = (sbuf + SM_AH + (uint32_t)c * 16) ^ ((((uint32_t)c >> 3) & 7) << 4);
        asm volatile("st.shared.v4.b32 [%0], {%1,%2,%3,%4};"
                     :: "r"(d), "r"(v.x), "r"(v.y), "r"(v.z), "r"(v.w));
        asm volatile("st.shared.v4.b32 [%0], {%1,%2,%3,%4};"
                     :: "r"(d + 16384), "r"(w.x), "r"(w.y), "r"(w.z), "r"(w.w));
    }
}

// ---------------- core: one K=64 GEMM (128x64 tile), 3-pass split ---------
__device__ __forceinline__ void gemm64(uint32_t sbuf, int mrow, int ncol, int lane,
                                       float (&acc)[2][4][4]) {
    const uint32_t xv = (uint32_t)(lane & 7) << 4;
    const uint32_t abase = sbuf + SM_AH + ((uint32_t)mrow + (uint32_t)(lane & 15)) * 128
                         + (uint32_t)(lane >> 4) * 16;
    const uint32_t bbase = sbuf + SM_BH
                         + ((uint32_t)ncol + (uint32_t)((lane & 7) + ((lane >> 4) << 3))) * 128
                         + (uint32_t)((lane & 8) << 1);
#pragma unroll
    for (int kk = 0; kk < 4; kk++) {
        const uint32_t k2b = kk * 32;
        uint32_t ah[2][4], al[2][4], bh[2][4], bl[2][4];
#pragma unroll
        for (int mf = 0; mf < 2; mf++) {
            uint32_t a = (abase + mf * 2048 + k2b) ^ xv;
            LDSM4(ah[mf], a);
            LDSM4(al[mf], a + 16384);
        }
#pragma unroll
        for (int nb = 0; nb < 2; nb++) {
            uint32_t a = (bbase + nb * 2048 + k2b) ^ xv;
            LDSM4(bh[nb], a);
            LDSM4(bl[nb], a + 8192);
        }
#pragma unroll
        for (int mf = 0; mf < 2; mf++)
#pragma unroll
            for (int nf = 0; nf < 4; nf++) {
                uint32_t B0 = bh[nf >> 1][(nf & 1) * 2], B1 = bh[nf >> 1][(nf & 1) * 2 + 1];
                uint32_t L0 = bl[nf >> 1][(nf & 1) * 2], L1 = bl[nf >> 1][(nf & 1) * 2 + 1];
                MMA_BF16(acc[mf][nf], ah[mf], B0, B1);
                MMA_BF16(acc[mf][nf], ah[mf], L0, L1);
                MMA_BF16(acc[mf][nf], al[mf], B0, B1);
            }
    }
}

// --------------------------------------------------------------------------
// prep: weight splits + bsum
// --------------------------------------------------------------------------
__global__ void prep(const float* __restrict__ wl, const float* __restrict__ wr,
                     const float* __restrict__ diag, const float* __restrict__ br,
                     const float* __restrict__ bias) {
    int i = blockIdx.x * 256 + threadIdx.x;
    if (i < 262144) {
        float v = wl[i];
        __nv_bfloat16 h = __float2bfloat16(v);
        g_wlh[i] = h;
        g_wll[i] = __float2bfloat16(v - __bfloat162float(h));
    } else if (i < 524288) {
        int k = i - 262144;
        float v = wr[k];
        __nv_bfloat16 h = __float2bfloat16(v);
        g_wrh[k] = h;
        g_wrl[k] = __float2bfloat16(v - __bfloat162float(h));
    } else if (i < 786432) {
        int k = i - 524288;             // dt layout [j][n][kk]
        int j = k >> 12, r = k & 4095, n = r >> 6, kk = r & 63;
        float v = diag[(size_t)j * 4096 + (size_t)kk * 64 + n];
        __nv_bfloat16 h = __float2bfloat16(v);
        g_dth[k] = h;
        g_dtl[k] = __float2bfloat16(v - __bfloat162float(h));
    } else if (i < 786432 + 4096) {
        int k = i - 786432;
        g_bsum[k] = br[k] + bias[k];
    }
}

// --------------------------------------------------------------------------
// k1: t_part[s] = x[:, 512s:512s+512] @ Wl^T slice, pipelined over 8 chunks.
// grid 512 (= 64 m-tiles x 8 k-splits), 256 threads, 2 CTAs/SM.
// --------------------------------------------------------------------------
__global__ void __launch_bounds__(256, 2)
k1_lowrank(const float* __restrict__ x) {
    extern __shared__ __align__(16) char smc[];
    const uint32_t sb = smem_u32(smc);
    const int tid = threadIdx.x, w = tid >> 5, lane = tid & 31;
    const int g = lane >> 2, q = lane & 3;
    const int m0 = (blockIdx.x >> 3) * 128;
    const int ks = (blockIdx.x & 7) * 512;
    const int mrow = (w & 3) * 32, ncol = (w >> 2) * 32;

    float acc[2][4][4];
#pragma unroll
    for (int mf = 0; mf < 2; mf++)
#pragma unroll
        for (int nf = 0; nf < 4; nf++)
#pragma unroll
            for (int cc = 0; cc < 4; cc++) acc[mf][nf][cc] = 0.0f;

    float4 xv[8];
    // prologue: stage chunk 0 into buf0
    ldg_x(xv, x + (size_t)m0 * IN_F + ks, tid);
    sts_x(sb, xv, tid);
    stage_Bwl(sb, ks, tid);
    __syncthreads();

    for (int c = 0; c < 8; c++) {
        const uint32_t bcur = sb + (uint32_t)(c & 1) * BUFSZ;
        const uint32_t bnxt = sb + (uint32_t)((c + 1) & 1) * BUFSZ;
        if (c < 7) ldg_x(xv, x + (size_t)m0 * IN_F + ks + (c + 1) * 64, tid);
        gemm64(bcur, mrow, ncol, lane, acc);
        if (c < 7) {
            sts_x(bnxt, xv, tid);
            stage_Bwl(bnxt, ks + (c + 1) * 64, tid);
        }
        __syncthreads();
    }

    float* tp = g_tpart[blockIdx.x & 7];
#pragma unroll
    for (int mf = 0; mf < 2; mf++)
#pragma unroll
        for (int nf = 0; nf < 4; nf++) {
            int row = m0 + mrow + mf * 16 + g;
            int col = ncol + nf * 8 + q * 2;
            *(float2*)&tp[(size_t)row * 64 + col] =
                make_float2(acc[mf][nf][0], acc[mf][nf][1]);
            *(float2*)&tp[(size_t)(row + 8) * 64 + col] =
                make_float2(acc[mf][nf][2], acc[mf][nf][3]);
        }
}

// --------------------------------------------------------------------------
// k1b: t = sum of partials -> bf16 hi/lo
// --------------------------------------------------------------------------
__global__ void k1b_reduce() {
    int i = blockIdx.x * 256 + threadIdx.x;
    float s = 0.0f;
#pragma unroll
    for (int p = 0; p < KSPLIT; p++) s += g_tpart[p][i];
    __nv_bfloat16 h = __float2bfloat16(s);
    g_thi[i] = h;
    g_tlo[i] = __float2bfloat16(s - __bfloat162float(h));
}

// --------------------------------------------------------------------------
// k2: out[m0:m0+128, 64j:64j+64] = xb_j @ D_j + t @ Wr_j^T + bsum,
// NJ=8 j's per CTA, two pipelined phases per j (gemm1 buf0, gemm2 buf1).
// grid (64 m, 8 jg), 256 threads, 2 CTAs/SM.
// --------------------------------------------------------------------------
__global__ void __launch_bounds__(256, 2)
k2_output(const float* __restrict__ x, float* __restrict__ out) {
    extern __shared__ __align__(16) char smc[];
    const uint32_t sb = smem_u32(smc);
    const int tid = threadIdx.x, w = tid >> 5, lane = tid & 31;
    const int g = lane >> 2, q = lane & 3;
    const int m0 = blockIdx.x * 128;
    const int jbase = blockIdx.y * NJ;
    const int mrow = (w & 3) * 32, ncol = (w >> 2) * 32;

    float acc[2][4][4];
#pragma unroll
    for (int mf = 0; mf < 2; mf++)
#pragma unroll
        for (int nf = 0; nf < 4; nf++)
#pragma unroll
            for (int cc = 0; cc < 4; cc++) acc[mf][nf][cc] = 0.0f;

    float4 xv[8];
    // prologue: stage gemm1 of j0 into buf0
    ldg_x(xv, x + (size_t)m0 * IN_F + jbase * 64, tid);
    sts_x(sb, xv, tid);
    stage_B64(sb, g_dth + (size_t)jbase * 4096, g_dtl + (size_t)jbase * 4096, tid);
    __syncthreads();

    for (int jj = 0; jj < NJ; jj++) {
        const int j = jbase + jj;
        const uint32_t buf0 = sb;            // gemm1 buffer
        const uint32_t buf1 = sb + BUFSZ;    // gemm2 buffer

        // phase A: compute gemm1(j) from buf0; stage gemm2(j) [t + Wr_j] -> buf1
        gemm64(buf0, mrow, ncol, lane, acc);
        stage_At(buf1, g_thi + (size_t)m0 * 64, g_tlo + (size_t)m0 * 64, tid);
        stage_B64(buf1, g_wrh + (size_t)j * 4096, g_wrl + (size_t)j * 4096, tid);
        __syncthreads();

        // phase B: compute gemm2(j) from buf1; stage gemm1(j+1) [x + D] -> buf0
        if (jj + 1 < NJ)
            ldg_x(xv, x + (size_t)m0 * IN_F + (j + 1) * 64, tid);
        gemm64(buf1, mrow, ncol, lane, acc);
        if (jj + 1 < NJ) {
            sts_x(buf0, xv, tid);
            stage_B64(buf0, g_dth + (size_t)(j + 1) * 4096,
                      g_dtl + (size_t)(j + 1) * 4096, tid);
        }

        // epilogue for j: write acc + bsum, reset acc (overlaps next phase)
        const float* bs = g_bsum + j * 64;
#pragma unroll
        for (int mf = 0; mf < 2; mf++)
#pragma unroll
            for (int nf = 0; nf < 4; nf++) {
                int col = ncol + nf * 8 + q * 2;
                int row = m0 + mrow + mf * 16 + g;
                float2 b = *(const float2*)(bs + col);
                *(float2*)&out[(size_t)row * OUT_F + j * 64 + col] =
                    make_float2(acc[mf][nf][0] + b.x, acc[mf][nf][1] + b.y);
                *(float2*)&out[(size_t)(row + 8) * OUT_F + j * 64 + col] =
                    make_float2(acc[mf][nf][2] + b.x, acc[mf][nf][3] + b.y);
                acc[mf][nf][0] = 0.0f; acc[mf][nf][1] = 0.0f;
                acc[mf][nf][2] = 0.0f; acc[mf][nf][3] = 0.0f;
            }
        __syncthreads();
    }
}

// --------------------------------------------------------------------------
extern "C" void kernel_launch(void* const* d_in, const int* in_sizes, int n_in,
                              void* d_out, int out_size) {
    const float* x    = (const float*)d_in[0];
    const float* diag = (const float*)d_in[1];
    const float* wl   = (const float*)d_in[2];
    const float* wrt  = (const float*)d_in[3];
    const float* br   = (const float*)d_in[4];
    const float* bias = (const float*)d_in[5];
    float* out = (float*)d_out;

    cudaFuncSetAttribute(k1_lowrank, cudaFuncAttributeMaxDynamicSharedMemorySize, SMEM_BYTES);
    cudaFuncSetAttribute(k2_output,  cudaFuncAttributeMaxDynamicSharedMemorySize, SMEM_BYTES);

    prep<<<3088, 256>>>(wl, wrt, diag, br, bias);
    k1_lowrank<<<512, 256, SMEM_BYTES>>>(x);
    k1b_reduce<<<2048, 256>>>();
    k2_output<<<dim3(64, 8), 256, SMEM_BYTES>>>(x, out);
}

// round 16
// speedup vs baseline: 1.2753x; 1.2753x over previous
#include <cuda_runtime.h>
#include <cuda_fp16.h>
#include <cstdint>

// ==========================================================================
// LORI_FC: out = x @ blockdiag(D) + (x @ Wl^T) @ Wr^T + (b_right + bias)
//   x [8192,4096] f32. Single-pass FP16 HMMA m16n8k16, f32 accumulate.
// Coalesced LDG -> swizzled STS -> ldmatrix.x4 -> MMA (R12 engine, fp16).
//   prep: convert Wl/Wr/D^T -> f16, bsum = br + bias
//   k1:   t_part[s] = x[:, 512s:512s+512] @ Wl^T slice   (512 CTAs)
//   k1b:  t = sum partials -> f16
//   k2:   out[128, 64j] = xb_j @ D_j + t @ Wr_j^T + bsum (4096 CTAs)
// ==========================================================================

#define M_ROWS 8192
#define IN_F   4096
#define OUT_F  4096
#define KSPLIT 8

__device__ __align__(16) float g_tpart[KSPLIT][M_ROWS * 64];       // 16 MB
__device__ __align__(16) __half g_th[M_ROWS * 64];
__device__ __align__(16) __half g_wl[64 * IN_F];
__device__ __align__(16) __half g_wr[OUT_F * 64];
__device__ __align__(16) __half g_dt[64 * 64 * 64];                // [j][n][k]
__device__ __align__(16) float g_bsum[OUT_F];

// smem layout (24 KB): A 16K (128 rows x 128B) | B 8K (64 rows x 128B)
#define SM_A 0
#define SM_B 16384
#define SMEM_BYTES 24576

#define MMA_F16(C, A, B0, B1)                                                 \
    asm volatile(                                                             \
        "mma.sync.aligned.m16n8k16.row.col.f32.f16.f16.f32 "                  \
        "{%0,%1,%2,%3}, {%4,%5,%6,%7}, {%8,%9}, {%0,%1,%2,%3};"               \
        : "+f"((C)[0]), "+f"((C)[1]), "+f"((C)[2]), "+f"((C)[3])              \
        : "r"((A)[0]), "r"((A)[1]), "r"((A)[2]), "r"((A)[3]), "r"(B0), "r"(B1))

#define LDSM4(R, A)                                                           \
    asm volatile("ldmatrix.sync.aligned.m8n8.x4.shared.b16 {%0,%1,%2,%3}, [%4];" \
        : "=r"((R)[0]), "=r"((R)[1]), "=r"((R)[2]), "=r"((R)[3]) : "r"(A))

__device__ __forceinline__ uint32_t smem_u32(const void* p) {
    uint32_t a;
    asm("{ .reg .u64 t; cvta.to.shared.u64 t, %1; cvt.u32.u64 %0, t; }"
        : "=r"(a) : "l"(p));
    return a;
}

// pack two f32 -> f16x2 (lo = f0, hi = f1)
__device__ __forceinline__ uint32_t pack_h2(float f0, float f1) {
    uint32_t h;
    asm("cvt.rn.f16x2.f32 %0, %1, %2;" : "=r"(h) : "f"(f1), "f"(f0));
    return h;
}

// ---------------- staging (coalesced LDG -> swizzled STS) ----------------
// A tile: 128 rows x 64 f16 (128B rows), XOR swizzle by (row&7)<<4.
// B tile:  64 rows x 64 f16.

// x block 128x64 f32 -> f16 A tile
__device__ __forceinline__ void stage_x(uint32_t sbuf, const float* xp, int tid) {
    const int r = tid >> 1, h = tid & 1;
    const float* p = xp + (size_t)r * IN_F + h * 32;
    const uint32_t dbase = sbuf + SM_A + (uint32_t)r * 128 + (uint32_t)h * 64;
    const uint32_t xv = (uint32_t)(r & 7) << 4;
#pragma unroll
    for (int i = 0; i < 8; i++) {
        float4 v = ((const float4*)p)[i];
        uint32_t h0 = pack_h2(v.x, v.y);
        uint32_t h1 = pack_h2(v.z, v.w);
        uint32_t d = (dbase + i * 8) ^ xv;
        asm volatile("st.shared.v2.b32 [%0], {%1,%2};" :: "r"(d), "r"(h0), "r"(h1));
    }
}

// f16 [64][64] contiguous -> B tile
__device__ __forceinline__ void stage_B64(uint32_t sbuf, const __half* src, int tid) {
#pragma unroll
    for (int c = tid; c < 512; c += 256) {
        uint4 v = ((const uint4*)src)[c];
        uint32_t d = (sbuf + SM_B + (uint32_t)c * 16) ^ ((((uint32_t)c >> 3) & 7) << 4);
        asm volatile("st.shared.v4.b32 [%0], {%1,%2,%3,%4};"
                     :: "r"(d), "r"(v.x), "r"(v.y), "r"(v.z), "r"(v.w));
    }
}

// Wl chunk (row stride IN_F), cols [kbase, kbase+64) -> B tile
__device__ __forceinline__ void stage_Bwl(uint32_t sbuf, int kbase, int tid) {
#pragma unroll
    for (int c = tid; c < 512; c += 256) {
        int n = c >> 3, kp = c & 7;
        uint4 v = *(const uint4*)(g_wl + (size_t)n * IN_F + kbase + kp * 8);
        uint32_t d = (sbuf + SM_B + (uint32_t)c * 16) ^ (((uint32_t)n & 7) << 4);
        asm volatile("st.shared.v4.b32 [%0], {%1,%2,%3,%4};"
                     :: "r"(d), "r"(v.x), "r"(v.y), "r"(v.z), "r"(v.w));
    }
}

// f16 t 128x64 contiguous -> A tile
__device__ __forceinline__ void stage_At(uint32_t sbuf, const __half* src, int tid) {
#pragma unroll
    for (int c = tid; c < 1024; c += 256) {
        uint4 v = ((const uint4*)src)[c];
        uint32_t d = (sbuf + SM_A + (uint32_t)c * 16) ^ ((((uint32_t)c >> 3) & 7) << 4);
        asm volatile("st.shared.v4.b32 [%0], {%1,%2,%3,%4};"
                     :: "r"(d), "r"(v.x), "r"(v.y), "r"(v.z), "r"(v.w));
    }
}

// ---------------- core: one K=64 GEMM (128x64 tile), single pass ---------
__device__ __forceinline__ void gemm64(uint32_t sbuf, int mrow, int ncol, int lane,
                                       float (&acc)[2][4][4]) {
    const uint32_t xv = (uint32_t)(lane & 7) << 4;
    const uint32_t abase = sbuf + SM_A + ((uint32_t)mrow + (uint32_t)(lane & 15)) * 128
                         + (uint32_t)(lane >> 4) * 16;
    const uint32_t bbase = sbuf + SM_B
                         + ((uint32_t)ncol + (uint32_t)((lane & 7) + ((lane >> 4) << 3))) * 128
                         + (uint32_t)((lane & 8) << 1);
#pragma unroll
    for (int kk = 0; kk < 4; kk++) {
        const uint32_t k2b = kk * 32;
        uint32_t ah[2][4], bh[2][4];
#pragma unroll
        for (int mf = 0; mf < 2; mf++)
            LDSM4(ah[mf], (abase + mf * 2048 + k2b) ^ xv);
#pragma unroll
        for (int nb = 0; nb < 2; nb++)
            LDSM4(bh[nb], (bbase + nb * 2048 + k2b) ^ xv);
#pragma unroll
        for (int mf = 0; mf < 2; mf++)
#pragma unroll
            for (int nf = 0; nf < 4; nf++)
                MMA_F16(acc[mf][nf], ah[mf],
                        bh[nf >> 1][(nf & 1) * 2], bh[nf >> 1][(nf & 1) * 2 + 1]);
    }
}

// --------------------------------------------------------------------------
// prep: weight conversion + bsum
// --------------------------------------------------------------------------
__global__ void prep(const float* __restrict__ wl, const float* __restrict__ wr,
                     const float* __restrict__ diag, const float* __restrict__ br,
                     const float* __restrict__ bias) {
    int i = blockIdx.x * 256 + threadIdx.x;
    if (i < 262144) {
        g_wl[i] = __float2half_rn(wl[i]);
    } else if (i < 524288) {
        int k = i - 262144;
        g_wr[k] = __float2half_rn(wr[k]);
    } else if (i < 786432) {
        int k = i - 524288;             // dt layout [j][n][kk]
        int j = k >> 12, r = k & 4095, n = r >> 6, kk = r & 63;
        g_dt[k] = __float2half_rn(diag[(size_t)j * 4096 + (size_t)kk * 64 + n]);
    } else if (i < 786432 + 4096) {
        int k = i - 786432;
        g_bsum[k] = br[k] + bias[k];
    }
}

// --------------------------------------------------------------------------
// k1: t_part[s] = x[:, 512s:512s+512] @ Wl^T slice.
// grid 512 (= 64 m-tiles x 8 k-splits), 256 threads.
// --------------------------------------------------------------------------
__global__ void __launch_bounds__(256, 3)
k1_lowrank(const float* __restrict__ x) {
    extern __shared__ __align__(16) char smc[];
    const uint32_t sb = smem_u32(smc);
    const int tid = threadIdx.x, w = tid >> 5, lane = tid & 31;
    const int g = lane >> 2, q = lane & 3;
    const int m0 = (blockIdx.x >> 3) * 128;
    const int ks = (blockIdx.x & 7) * 512;
    const int mrow = (w & 3) * 32, ncol = (w >> 2) * 32;

    float acc[2][4][4];
#pragma unroll
    for (int mf = 0; mf < 2; mf++)
#pragma unroll
        for (int nf = 0; nf < 4; nf++)
#pragma unroll
            for (int cc = 0; cc < 4; cc++) acc[mf][nf][cc] = 0.0f;

    for (int c = 0; c < 8; c++) {
        stage_x(sb, x + (size_t)m0 * IN_F + ks + c * 64, tid);
        stage_Bwl(sb, ks + c * 64, tid);
        __syncthreads();
        gemm64(sb, mrow, ncol, lane, acc);
        __syncthreads();
    }

    float* tp = g_tpart[blockIdx.x & 7];
#pragma unroll
    for (int mf = 0; mf < 2; mf++)
#pragma unroll
        for (int nf = 0; nf < 4; nf++) {
            int row = m0 + mrow + mf * 16 + g;
            int col = ncol + nf * 8 + q * 2;
            *(float2*)&tp[(size_t)row * 64 + col] =
                make_float2(acc[mf][nf][0], acc[mf][nf][1]);
            *(float2*)&tp[(size_t)(row + 8) * 64 + col] =
                make_float2(acc[mf][nf][2], acc[mf][nf][3]);
        }
}

// --------------------------------------------------------------------------
// k1b: t = sum of partials -> f16
// --------------------------------------------------------------------------
__global__ void k1b_reduce() {
    int i = blockIdx.x * 256 + threadIdx.x;
    float s = 0.0f;
#pragma unroll
    for (int p = 0; p < KSPLIT; p++) s += g_tpart[p][i];
    g_th[i] = __float2half_rn(s);
}

// --------------------------------------------------------------------------
// k2: out[m0:m0+128, 64j:64j+64] = xb_j @ D_j + t @ Wr_j^T + bsum
// grid (64 m, 64 j), 256 threads, 3 CTAs/SM.
// --------------------------------------------------------------------------
__global__ void __launch_bounds__(256, 3)
k2_output(const float* __restrict__ x, float* __restrict__ out) {
    extern __shared__ __align__(16) char smc[];
    const uint32_t sb = smem_u32(smc);
    const int tid = threadIdx.x, w = tid >> 5, lane = tid & 31;
    const int g = lane >> 2, q = lane & 3;
    const int m0 = blockIdx.x * 128;
    const int j  = blockIdx.y;
    const int mrow = (w & 3) * 32, ncol = (w >> 2) * 32;

    float acc[2][4][4];
#pragma unroll
    for (int mf = 0; mf < 2; mf++)
#pragma unroll
        for (int nf = 0; nf < 4; nf++)
#pragma unroll
            for (int cc = 0; cc < 4; cc++) acc[mf][nf][cc] = 0.0f;

    // GEMM 1: A = x[:, 64j:64j+64], B = D_j^T
    stage_x(sb, x + (size_t)m0 * IN_F + j * 64, tid);
    stage_B64(sb, g_dt + (size_t)j * 4096, tid);
    __syncthreads();
    gemm64(sb, mrow, ncol, lane, acc);
    __syncthreads();

    // GEMM 2: A = t (f16), B = Wr_j
    stage_At(sb, g_th + (size_t)m0 * 64, tid);
    stage_B64(sb, g_wr + (size_t)j * 4096, tid);
    __syncthreads();
    gemm64(sb, mrow, ncol, lane, acc);

    // epilogue: + bsum
    const float* bs = g_bsum + j * 64;
#pragma unroll
    for (int mf = 0; mf < 2; mf++)
#pragma unroll
        for (int nf = 0; nf < 4; nf++) {
            int col = ncol + nf * 8 + q * 2;
            int row = m0 + mrow + mf * 16 + g;
            float2 b = *(const float2*)(bs + col);
            *(float2*)&out[(size_t)row * OUT_F + j * 64 + col] =
                make_float2(acc[mf][nf][0] + b.x, acc[mf][nf][1] + b.y);
            *(float2*)&out[(size_t)(row + 8) * OUT_F + j * 64 + col] =
                make_float2(acc[mf][nf][2] + b.x, acc[mf][nf][3] + b.y);
        }
}

// --------------------------------------------------------------------------
extern "C" void kernel_launch(void* const* d_in, const int* in_sizes, int n_in,
                              void* d_out, int out_size) {
    const float* x    = (const float*)d_in[0];
    const float* diag = (const float*)d_in[1];
    const float* wl   = (const float*)d_in[2];
    const float* wrt  = (const float*)d_in[3];
    const float* br   = (const float*)d_in[4];
    const float* bias = (const float*)d_in[5];
    float* out = (float*)d_out;

    cudaFuncSetAttribute(k1_lowrank, cudaFuncAttributeMaxDynamicSharedMemorySize, SMEM_BYTES);
    cudaFuncSetAttribute(k2_output,  cudaFuncAttributeMaxDynamicSharedMemorySize, SMEM_BYTES);

    prep<<<3088, 256>>>(wl, wrt, diag, br, bias);
    k1_lowrank<<<512, 256, SMEM_BYTES>>>(x);
    k1b_reduce<<<2048, 256>>>();
    k2_output<<<dim3(64, 64), 256, SMEM_BYTES>>>(x, out);
}

// round 17
// speedup vs baseline: 1.4758x; 1.1572x over previous
#include <cuda_runtime.h>
#include <cuda_fp16.h>
#include <cstdint>

// ==========================================================================
// LORI_FC: out = x @ blockdiag(D) + (x @ Wl^T) @ Wr^T + (b_right + bias)
//   x [8192,4096] f32. Single-pass FP16 HMMA m16n8k16, f32 accumulate.
// Coalesced LDG -> swizzled STS -> ldmatrix.x4 -> MMA.
//   prep: convert Wl/Wr/D^T -> f16, bsum = br + bias
//   k1:   t_part[s] = x[:, 256s:256s+256] @ Wl^T slice   (1024 CTAs)
//   k1b:  t = sum partials -> f16
//   k2:   out[128, 64j] = xb_j @ D_j + t @ Wr_j^T + bsum (4096 CTAs)
// ==========================================================================

#define M_ROWS 8192
#define IN_F   4096
#define OUT_F  4096
#define KSPLIT 16

__device__ __align__(16) float g_tpart[KSPLIT][M_ROWS * 64];       // 32 MB
__device__ __align__(16) __half g_th[M_ROWS * 64];
__device__ __align__(16) __half g_wl[64 * IN_F];
__device__ __align__(16) __half g_wr[OUT_F * 64];
__device__ __align__(16) __half g_dt[64 * 64 * 64];                // [j][n][k]
__device__ __align__(16) float g_bsum[OUT_F];

// smem layout (24 KB): A 16K (128 rows x 128B) | B 8K (64 rows x 128B)
#define SM_A 0
#define SM_B 16384
#define SMEM_BYTES 24576

#define MMA_F16(C, A, B0, B1)                                                 \
    asm volatile(                                                             \
        "mma.sync.aligned.m16n8k16.row.col.f32.f16.f16.f32 "                  \
        "{%0,%1,%2,%3}, {%4,%5,%6,%7}, {%8,%9}, {%0,%1,%2,%3};"               \
        : "+f"((C)[0]), "+f"((C)[1]), "+f"((C)[2]), "+f"((C)[3])              \
        : "r"((A)[0]), "r"((A)[1]), "r"((A)[2]), "r"((A)[3]), "r"(B0), "r"(B1))

#define LDSM4(R, A)                                                           \
    asm volatile("ldmatrix.sync.aligned.m8n8.x4.shared.b16 {%0,%1,%2,%3}, [%4];" \
        : "=r"((R)[0]), "=r"((R)[1]), "=r"((R)[2]), "=r"((R)[3]) : "r"(A))

__device__ __forceinline__ uint32_t smem_u32(const void* p) {
    uint32_t a;
    asm("{ .reg .u64 t; cvta.to.shared.u64 t, %1; cvt.u32.u64 %0, t; }"
        : "=r"(a) : "l"(p));
    return a;
}

// pack two f32 -> f16x2 (lo = f0, hi = f1)
__device__ __forceinline__ uint32_t pack_h2(float f0, float f1) {
    uint32_t h;
    asm("cvt.rn.f16x2.f32 %0, %1, %2;" : "=r"(h) : "f"(f1), "f"(f0));
    return h;
}

// ---------------- staging (coalesced LDG -> swizzled STS) ----------------
// A tile: 128 rows x 64 f16 (128B rows), XOR swizzle by (row&7)<<4.
// B tile:  64 rows x 64 f16.

// x block 128x64 f32 -> f16 A tile
__device__ __forceinline__ void stage_x(uint32_t sbuf, const float* xp, int tid) {
    const int r = tid >> 1, h = tid & 1;
    const float* p = xp + (size_t)r * IN_F + h * 32;
    const uint32_t dbase = sbuf + SM_A + (uint32_t)r * 128 + (uint32_t)h * 64;
    const uint32_t xv = (uint32_t)(r & 7) << 4;
#pragma unroll
    for (int i = 0; i < 8; i++) {
        float4 v = ((const float4*)p)[i];
        uint32_t h0 = pack_h2(v.x, v.y);
        uint32_t h1 = pack_h2(v.z, v.w);
        uint32_t d = (dbase + i * 8) ^ xv;
        asm volatile("st.shared.v2.b32 [%0], {%1,%2};" :: "r"(d), "r"(h0), "r"(h1));
    }
}

// f16 [64][64] contiguous -> B tile
__device__ __forceinline__ void stage_B64(uint32_t sbuf, const __half* src, int tid) {
#pragma unroll
    for (int c = tid; c < 512; c += 256) {
        uint4 v = ((const uint4*)src)[c];
        uint32_t d = (sbuf + SM_B + (uint32_t)c * 16) ^ ((((uint32_t)c >> 3) & 7) << 4);
        asm volatile("st.shared.v4.b32 [%0], {%1,%2,%3,%4};"
                     :: "r"(d), "r"(v.x), "r"(v.y), "r"(v.z), "r"(v.w));
    }
}

// Wl chunk (row stride IN_F), cols [kbase, kbase+64) -> B tile
__device__ __forceinline__ void stage_Bwl(uint32_t sbuf, int kbase, int tid) {
#pragma unroll
    for (int c = tid; c < 512; c += 256) {
        int n = c >> 3, kp = c & 7;
        uint4 v = *(const uint4*)(g_wl + (size_t)n * IN_F + kbase + kp * 8);
        uint32_t d = (sbuf + SM_B + (uint32_t)c * 16) ^ (((uint32_t)n & 7) << 4);
        asm volatile("st.shared.v4.b32 [%0], {%1,%2,%3,%4};"
                     :: "r"(d), "r"(v.x), "r"(v.y), "r"(v.z), "r"(v.w));
    }
}

// f16 t 128x64 contiguous -> A tile
__device__ __forceinline__ void stage_At(uint32_t sbuf, const __half* src, int tid) {
#pragma unroll
    for (int c = tid; c < 1024; c += 256) {
        uint4 v = ((const uint4*)src)[c];
        uint32_t d = (sbuf + SM_A + (uint32_t)c * 16) ^ ((((uint32_t)c >> 3) & 7) << 4);
        asm volatile("st.shared.v4.b32 [%0], {%1,%2,%3,%4};"
                     :: "r"(d), "r"(v.x), "r"(v.y), "r"(v.z), "r"(v.w));
    }
}

// ---------------- core: one K=64 GEMM (128x64 tile), single pass ---------
__device__ __forceinline__ void gemm64(uint32_t sbuf, int mrow, int ncol, int lane,
                                       float (&acc)[2][4][4]) {
    const uint32_t xv = (uint32_t)(lane & 7) << 4;
    const uint32_t abase = sbuf + SM_A + ((uint32_t)mrow + (uint32_t)(lane & 15)) * 128
                         + (uint32_t)(lane >> 4) * 16;
    const uint32_t bbase = sbuf + SM_B
                         + ((uint32_t)ncol + (uint32_t)((lane & 7) + ((lane >> 4) << 3))) * 128
                         + (uint32_t)((lane & 8) << 1);
#pragma unroll
    for (int kk = 0; kk < 4; kk++) {
        const uint32_t k2b = kk * 32;
        uint32_t ah[2][4], bh[2][4];
#pragma unroll
        for (int mf = 0; mf < 2; mf++)
            LDSM4(ah[mf], (abase + mf * 2048 + k2b) ^ xv);
#pragma unroll
        for (int nb = 0; nb < 2; nb++)
            LDSM4(bh[nb], (bbase + nb * 2048 + k2b) ^ xv);
#pragma unroll
        for (int mf = 0; mf < 2; mf++)
#pragma unroll
            for (int nf = 0; nf < 4; nf++)
                MMA_F16(acc[mf][nf], ah[mf],
                        bh[nf >> 1][(nf & 1) * 2], bh[nf >> 1][(nf & 1) * 2 + 1]);
    }
}

// --------------------------------------------------------------------------
// prep: weight conversion + bsum
// --------------------------------------------------------------------------
__global__ void prep(const float* __restrict__ wl, const float* __restrict__ wr,
                     const float* __restrict__ diag, const float* __restrict__ br,
                     const float* __restrict__ bias) {
    int i = blockIdx.x * 256 + threadIdx.x;
    if (i < 262144) {
        g_wl[i] = __float2half_rn(wl[i]);
    } else if (i < 524288) {
        int k = i - 262144;
        g_wr[k] = __float2half_rn(wr[k]);
    } else if (i < 786432) {
        int k = i - 524288;             // dt layout [j][n][kk]
        int j = k >> 12, r = k & 4095, n = r >> 6, kk = r & 63;
        g_dt[k] = __float2half_rn(diag[(size_t)j * 4096 + (size_t)kk * 64 + n]);
    } else if (i < 786432 + 4096) {
        int k = i - 786432;
        g_bsum[k] = br[k] + bias[k];
    }
}

// --------------------------------------------------------------------------
// k1: t_part[s] = x[:, 256s:256s+256] @ Wl^T slice.
// grid 1024 (= 64 m-tiles x 16 k-splits), 256 threads, 3 CTAs/SM.
// --------------------------------------------------------------------------
__global__ void __launch_bounds__(256, 3)
k1_lowrank(const float* __restrict__ x) {
    extern __shared__ __align__(16) char smc[];
    const uint32_t sb = smem_u32(smc);
    const int tid = threadIdx.x, w = tid >> 5, lane = tid & 31;
    const int g = lane >> 2, q = lane & 3;
    const int m0 = (blockIdx.x >> 4) * 128;
    const int ks = (blockIdx.x & 15) * 256;
    const int mrow = (w & 3) * 32, ncol = (w >> 2) * 32;

    float acc[2][4][4];
#pragma unroll
    for (int mf = 0; mf < 2; mf++)
#pragma unroll
        for (int nf = 0; nf < 4; nf++)
#pragma unroll
            for (int cc = 0; cc < 4; cc++) acc[mf][nf][cc] = 0.0f;

    for (int c = 0; c < 4; c++) {
        stage_x(sb, x + (size_t)m0 * IN_F + ks + c * 64, tid);
        stage_Bwl(sb, ks + c * 64, tid);
        __syncthreads();
        gemm64(sb, mrow, ncol, lane, acc);
        __syncthreads();
    }

    float* tp = g_tpart[blockIdx.x & 15];
#pragma unroll
    for (int mf = 0; mf < 2; mf++)
#pragma unroll
        for (int nf = 0; nf < 4; nf++) {
            int row = m0 + mrow + mf * 16 + g;
            int col = ncol + nf * 8 + q * 2;
            *(float2*)&tp[(size_t)row * 64 + col] =
                make_float2(acc[mf][nf][0], acc[mf][nf][1]);
            *(float2*)&tp[(size_t)(row + 8) * 64 + col] =
                make_float2(acc[mf][nf][2], acc[mf][nf][3]);
        }
}

// --------------------------------------------------------------------------
// k1b: t = sum of partials -> f16
// --------------------------------------------------------------------------
__global__ void k1b_reduce() {
    int i = blockIdx.x * 256 + threadIdx.x;
    float s = 0.0f;
#pragma unroll
    for (int p = 0; p < KSPLIT; p++) s += g_tpart[p][i];
    g_th[i] = __float2half_rn(s);
}

// --------------------------------------------------------------------------
// k2: out[m0:m0+128, 64j:64j+64] = xb_j @ D_j + t @ Wr_j^T + bsum
// grid (64 m, 64 j), 256 threads, 3 CTAs/SM.
// --------------------------------------------------------------------------
__global__ void __launch_bounds__(256, 3)
k2_output(const float* __restrict__ x, float* __restrict__ out) {
    extern __shared__ __align__(16) char smc[];
    const uint32_t sb = smem_u32(smc);
    const int tid = threadIdx.x, w = tid >> 5, lane = tid & 31;
    const int g = lane >> 2, q = lane & 3;
    const int m0 = blockIdx.x * 128;
    const int j  = blockIdx.y;
    const int mrow = (w & 3) * 32, ncol = (w >> 2) * 32;

    float acc[2][4][4];
#pragma unroll
    for (int mf = 0; mf < 2; mf++)
#pragma unroll
        for (int nf = 0; nf < 4; nf++)
#pragma unroll
            for (int cc = 0; cc < 4; cc++) acc[mf][nf][cc] = 0.0f;

    // GEMM 1: A = x[:, 64j:64j+64], B = D_j^T
    stage_x(sb, x + (size_t)m0 * IN_F + j * 64, tid);
    stage_B64(sb, g_dt + (size_t)j * 4096, tid);
    __syncthreads();
    gemm64(sb, mrow, ncol, lane, acc);
    __syncthreads();

    // GEMM 2: A = t (f16), B = Wr_j
    stage_At(sb, g_th + (size_t)m0 * 64, tid);
    stage_B64(sb, g_wr + (size_t)j * 4096, tid);
    __syncthreads();
    gemm64(sb, mrow, ncol, lane, acc);

    // epilogue: + bsum
    const float* bs = g_bsum + j * 64;
#pragma unroll
    for (int mf = 0; mf < 2; mf++)
#pragma unroll
        for (int nf = 0; nf < 4; nf++) {
            int col = ncol + nf * 8 + q * 2;
            int row = m0 + mrow + mf * 16 + g;
            float2 b = *(const float2*)(bs + col);
            *(float2*)&out[(size_t)row * OUT_F + j * 64 + col] =
                make_float2(acc[mf][nf][0] + b.x, acc[mf][nf][1] + b.y);
            *(float2*)&out[(size_t)(row + 8) * OUT_F + j * 64 + col] =
                make_float2(acc[mf][nf][2] + b.x, acc[mf][nf][3] + b.y);
        }
}

// --------------------------------------------------------------------------
extern "C" void kernel_launch(void* const* d_in, const int* in_sizes, int n_in,
                              void* d_out, int out_size) {
    const float* x    = (const float*)d_in[0];
    const float* diag = (const float*)d_in[1];
    const float* wl   = (const float*)d_in[2];
    const float* wrt  = (const float*)d_in[3];
    const float* br   = (const float*)d_in[4];
    const float* bias = (const float*)d_in[5];
    float* out = (float*)d_out;

    cudaFuncSetAttribute(k1_lowrank, cudaFuncAttributeMaxDynamicSharedMemorySize, SMEM_BYTES);
    cudaFuncSetAttribute(k2_output,  cudaFuncAttributeMaxDynamicSharedMemorySize, SMEM_BYTES);

    prep<<<3088, 256>>>(wl, wrt, diag, br, bias);
    k1_lowrank<<<1024, 256, SMEM_BYTES>>>(x);
    k1b_reduce<<<2048, 256>>>();
    k2_output<<<dim3(64, 64), 256, SMEM_BYTES>>>(x, out);
}